// round 14
// baseline (speedup 1.0000x reference)
#include <cuda_runtime.h>
#include <cuda_fp16.h>
#include <math.h>
#include <stdint.h>

// ---------------- workspace (device globals; allocations are forbidden) ----
__device__ __align__(16) __half g_stem_h[16*64*256*256]; // stem conv out, CHW fp16
__device__ __align__(16) float  g_fT  [16*128*128*64];   // f, HWC
__device__ __align__(16) float  g_xtT [2][16*128*128*64];// xt1/xt2, HWC
__device__ __align__(16) float  g_h   [16*529*704];      // roi concat, cell-major
__device__ __align__(16) float  g_c1  [16*64*441];       // conv1 out (b,oc,21,21)
__device__ __align__(16) float  g_p1  [16*64*100];       // pool1 out (b,oc,10,10)
__device__ __align__(16) float  g_c2  [16*2048];         // conv2 out flattened
__device__ __align__(16) float  g_fc  [16*128];
__device__ __align__(16) float  g_w1t [704*9*64];        // conv1_w transposed [ic][k][oc]
__device__ float g_ssum[64], g_ssq[64];
__device__ float g_sc0[64], g_sh0[64], g_sc1[64], g_sh1[64];

// ---------------- helpers -------------------------------------------------
__device__ __forceinline__ uint32_t smem_u32(const void* p) {
    uint32_t a;
    asm("{ .reg .u64 t; cvta.to.shared.u64 t, %1; cvt.u32.u64 %0, t; }"
        : "=r"(a) : "l"(p));
    return a;
}
__device__ __forceinline__ void ldsm4(uint32_t* r, uint32_t addr) {
    asm volatile("ldmatrix.sync.aligned.m8n8.x4.shared.b16 {%0,%1,%2,%3}, [%4];"
                 : "=r"(r[0]), "=r"(r[1]), "=r"(r[2]), "=r"(r[3]) : "r"(addr));
}
__device__ __forceinline__ void mma16816(float* d, const uint32_t* a,
                                         uint32_t b0, uint32_t b1) {
    asm volatile(
        "mma.sync.aligned.m16n8k16.row.col.f32.f16.f16.f32 "
        "{%0,%1,%2,%3}, {%4,%5,%6,%7}, {%8,%9}, {%0,%1,%2,%3};"
        : "+f"(d[0]), "+f"(d[1]), "+f"(d[2]), "+f"(d[3])
        : "r"(a[0]), "r"(a[1]), "r"(a[2]), "r"(a[3]), "r"(b0), "r"(b1));
}

// ---------------- K0: zero BN accumulators -------------------------------
__global__ void k_zero() {
    int t = threadIdx.x;
    if (t < 64) { g_ssum[t] = 0.f; g_ssq[t] = 0.f; }
}

// ---------------- K1: stem conv 7x7 s2 p3 via HMMA (mma.sync f16) --------
// grid (2,256,16)=(ow half, oh, b); block 128 (4 warps); dyn smem 76032 B
// smem: [0] s_sum 64f, [256] s_sq 64f, [512] A 128x168 half (43008B),
//       [43520] B 64x168 half (21504B), [65024] stage 7x784 half (10976B)
// epilogue reuses [512..34304) as s_out[64][132] f32
#define SMO_A    512
#define SMO_B    43520
#define SMO_STG  65024
#define STEM_SMEM 76032
#define KLD 168            // padded K stride in halves (336 B)

__global__ __launch_bounds__(128) void k_stemh(const float* __restrict__ x,
                                               const float* __restrict__ w) {
    extern __shared__ char smem[];
    const uint32_t sb = smem_u32(smem);
    float*  s_sum = (float*)(smem);
    float*  s_sq  = (float*)(smem + 256);
    __half* A     = (__half*)(smem + SMO_A);
    __half* Bm    = (__half*)(smem + SMO_B);
    __half* stg   = (__half*)(smem + SMO_STG);

    const int half = blockIdx.x, oh = blockIdx.y, b = blockIdx.z;
    const int tid = threadIdx.x;
    const int wid = tid >> 5, lane = tid & 31;

    if (tid < 64) { s_sum[tid] = 0.f; s_sq[tid] = 0.f; }

    // stage input rows (fp16): stage[kh][c3], row padded 783->784 for half2 align
    {
        const int iw0 = 2 * (half * 128) - 3;
        for (int i = tid; i < 7 * 784; i += 128) {
            int kh = i / 784, c3 = i - kh * 784;
            float v = 0.f;
            if (c3 < 783) {
                int ih = 2 * oh - 3 + kh;
                int col = c3 / 3;
                int iw = iw0 + col;
                if (ih >= 0 && ih < 512 && iw >= 0 && iw < 512)
                    v = x[(size_t)(b * 512 + ih) * 1536 + (size_t)iw0 * 3 + c3];
            }
            stg[i] = __float2half_rn(v);
        }
    }
    // B[oc][k], k = kh*22 + kw*3 + c, from w[oc][c][kh][kw]
    for (int i = tid; i < 64 * 147; i += 128) {
        int oc = i / 147, r = i - oc * 147;
        int c = r / 49, r2 = r - c * 49;
        int kh = r2 / 7, kw = r2 - kh * 7;
        Bm[oc * KLD + kh * 22 + kw * 3 + c] = __float2half_rn(w[i]);
    }
    // B pad columns: k = 22t+21 (t=0..6) and k = 154..159
    for (int i = tid; i < 64 * 13; i += 128) {
        int oc = i / 13, p = i - oc * 13;
        int k = (p < 7) ? (p * 22 + 21) : (147 + p);
        Bm[oc * KLD + k] = __float2half_rn(0.f);
    }
    __syncthreads();

    // im2col A[m][k], pure half2 copy: 21 contiguous stage halves @6m per kh
    {
        const int m = tid;
        #pragma unroll 1
        for (int kh = 0; kh < 7; kh++) {
            const __half* src = stg + kh * 784 + 6 * m;
            __half2 hv[10];
            #pragma unroll
            for (int j = 0; j < 10; j++) hv[j] = *(const __half2*)(src + 2 * j);
            __half v20 = src[20];
            __half2* dst = (__half2*)(A + m * KLD + kh * 22);
            #pragma unroll
            for (int j = 0; j < 10; j++) dst[j] = hv[j];
            dst[10] = __halves2half2(v20, __float2half_rn(0.f));
        }
        // tail pad k = 154..159
        __half2* dt = (__half2*)(A + m * KLD + 154);
        #pragma unroll
        for (int t = 0; t < 3; t++) dt[t] = __float2half2_rn(0.f);
    }
    __syncthreads();

    // ---- HMMA mainloop: 10 k-steps of 16 ----
    float acc[2][8][4];
    #pragma unroll
    for (int mt = 0; mt < 2; mt++)
        #pragma unroll
        for (int nt = 0; nt < 8; nt++)
            #pragma unroll
            for (int q = 0; q < 4; q++) acc[mt][nt][q] = 0.f;

    uint32_t aAddr[2], bAddr[4];
    #pragma unroll
    for (int mt = 0; mt < 2; mt++) {
        int m0 = wid * 32 + mt * 16;
        aAddr[mt] = sb + SMO_A
                  + ((m0 + (lane & 15)) * KLD + (lane >> 4) * 8) * 2;
    }
    #pragma unroll
    for (int bt = 0; bt < 4; bt++) {
        int n0 = bt * 16;
        bAddr[bt] = sb + SMO_B
                  + ((n0 + ((lane >> 4) << 3) + (lane & 7)) * KLD
                     + ((lane >> 3) & 1) * 8) * 2;
    }

    #pragma unroll
    for (int ks = 0; ks < 10; ks++) {
        uint32_t ra[2][4], rb[4][4];
        ldsm4(ra[0], aAddr[0] + ks * 32);
        ldsm4(ra[1], aAddr[1] + ks * 32);
        #pragma unroll
        for (int bt = 0; bt < 4; bt++) ldsm4(rb[bt], bAddr[bt] + ks * 32);
        #pragma unroll
        for (int mt = 0; mt < 2; mt++)
            #pragma unroll
            for (int nt = 0; nt < 8; nt++)
                mma16816(acc[mt][nt], ra[mt],
                         rb[nt >> 1][(nt & 1) * 2], rb[nt >> 1][(nt & 1) * 2 + 1]);
    }

    // ---- epilogue: transpose through smem, coalesced fp16 STG + BN stats ----
    __syncthreads();                       // done reading A/B
    float* s_out = (float*)(smem + SMO_A); // [64][132]
    {
        const int gr = lane >> 2;
        const int c2 = (lane & 3) * 2;
        #pragma unroll
        for (int mt = 0; mt < 2; mt++) {
            int m0 = wid * 32 + mt * 16 + gr;
            #pragma unroll
            for (int nt = 0; nt < 8; nt++) {
                int c = nt * 8 + c2;
                s_out[ c      * 132 + m0    ] = acc[mt][nt][0];
                s_out[(c + 1) * 132 + m0    ] = acc[mt][nt][1];
                s_out[ c      * 132 + m0 + 8] = acc[mt][nt][2];
                s_out[(c + 1) * 132 + m0 + 8] = acc[mt][nt][3];
            }
        }
    }
    __syncthreads();

    // coalesced fp16 store: warp w owns channels 16w..16w+15; 256B per instr
    {
        const size_t rowbase = ((size_t)(b * 64) * 256 + oh) * 256
                             + half * 128 + 4 * lane;      // in halves
        #pragma unroll
        for (int ci = 0; ci < 16; ci++) {
            int c = wid * 16 + ci;
            float4 v = *(float4*)&s_out[c * 132 + 4 * lane];
            __half2 h01 = __floats2half2_rn(v.x, v.y);
            __half2 h23 = __floats2half2_rn(v.z, v.w);
            uint2 u = make_uint2(*(uint32_t*)&h01, *(uint32_t*)&h23);
            *(uint2*)(g_stem_h + rowbase + (size_t)c * 65536) = u;
        }
    }
    // BN partials: 2 threads per channel (fp32, pre-rounding)
    {
        int c = tid >> 1, part = tid & 1;
        const float* p = &s_out[c * 132 + part * 64];
        float s = 0.f, q = 0.f;
        #pragma unroll
        for (int i = 0; i < 16; i++) {
            float4 v = *(const float4*)(p + 4 * i);
            s += v.x + v.y + v.z + v.w;
            q += v.x*v.x + v.y*v.y + v.z*v.z + v.w*v.w;
        }
        s += __shfl_xor_sync(0xffffffffu, s, 1);
        q += __shfl_xor_sync(0xffffffffu, q, 1);
        if (part == 0) { atomicAdd(&s_sum[c], s); atomicAdd(&s_sq[c], q); }
    }
    __syncthreads();
    if (tid < 64) {
        atomicAdd(&g_ssum[tid], s_sum[tid]);
        atomicAdd(&g_ssq [tid], s_sq [tid]);
    }
}

// ---------------- K3: stem BN finalize -----------------------------------
__global__ void k_fin0(const float* __restrict__ g, const float* __restrict__ bt) {
    int c = threadIdx.x; if (c >= 64) return;
    const double n = 1048576.0;
    double m   = (double)g_ssum[c] / n;
    double var = (double)g_ssq[c] / n - m*m;
    double sc  = (double)g[c] / sqrt(var + 1e-5);
    g_sc0[c] = (float)sc;
    g_sh0[c] = (float)((double)bt[c] - m*sc);
}

// ---------------- K4: fused BN+ReLU+maxpool3/2/1 + CHW->HWC => g_fT ------
// grid (128,16)=(oh,b); block 256 (8 warps)
__global__ __launch_bounds__(256) void k_poolt() {
    __shared__ float s_t[128][65];
    const int oh = blockIdx.x, b = blockIdx.y;
    const int tid = threadIdx.x;
    const int wid = tid >> 5, lane = tid & 31;
    const __half* base = g_stem_h + (size_t)b * 64 * 65536;

    for (int c = wid; c < 64; c += 8) {
        const __half* pc = base + (size_t)c * 65536;
        const float sc = g_sc0[c], sh = g_sh0[c];
        #pragma unroll
        for (int k = 0; k < 4; k++) {
            int ow = lane + 32 * k;
            float m = 0.f;
            #pragma unroll
            for (int kh = 0; kh < 3; kh++) {
                int ih = 2*oh - 1 + kh; if (ih < 0 || ih > 255) continue;
                #pragma unroll
                for (int kw = 0; kw < 3; kw++) {
                    int iw = 2*ow - 1 + kw; if (iw < 0 || iw > 255) continue;
                    m = fmaxf(m, fmaf(__half2float(pc[ih*256 + iw]), sc, sh));
                }
            }
            s_t[ow][c] = m;
        }
    }
    __syncthreads();
    float* ob = g_fT + (size_t)b * 1048576 + (size_t)oh * 128 * 64;
    for (int i = tid; i < 8192; i += 256) {
        int ow = i >> 6, c = i & 63;
        ob[i] = s_t[ow][c];
    }
}

// ---------------- K6: grid_sample (grid (16,128,2); block 256) -----------
__global__ void k_gsample() {
    const int b = blockIdx.x, y = blockIdx.y, rot = blockIdx.z;
    const int wid = threadIdx.x >> 5, lane = threadIdx.x & 31;
    const float cosv = 0.99619469809174553f;
    const float sinv = 0.08715574274765817f;
    const float t01 = rot ? -sinv : sinv;
    const float gy  = (2*y + 1) / 128.0f - 1.0f;
    const float* fb = g_fT + (size_t)b*1048576;
    float* ob = g_xtT[rot] + (size_t)b*1048576 + (size_t)y*128*64;

    for (int x = wid; x < 128; x += 8) {
        float gx = (2*x + 1) / 128.0f - 1.0f;
        float u = gx*cosv + gy*t01;
        float v = -gx*t01 + gy*cosv;
        float ix = ((u + 1.f)*128.f - 1.f)*0.5f;
        float iy = ((v + 1.f)*128.f - 1.f)*0.5f;
        float x0f = floorf(ix), y0f = floorf(iy);
        int x0 = (int)x0f, y0 = (int)y0f;
        float wa = (x0f + 1 - ix)*(y0f + 1 - iy);
        float wb = (x0f + 1 - ix)*(iy - y0f);
        float wc = (ix - x0f)*(y0f + 1 - iy);
        float wd = (ix - x0f)*(iy - y0f);
        bool vx0 = (x0 >= 0) && (x0 < 128), vx1 = (x0+1 >= 0) && (x0+1 < 128);
        bool vy0 = (y0 >= 0) && (y0 < 128), vy1 = (y0+1 >= 0) && (y0+1 < 128);
        int cx0 = min(max(x0,0),127),   cx1 = min(max(x0+1,0),127);
        int cy0 = min(max(y0,0),127),   cy1 = min(max(y0+1,0),127);
        float w00 = (vy0 && vx0) ? wa : 0.f;
        float w01 = (vy1 && vx0) ? wb : 0.f;
        float w10 = (vy0 && vx1) ? wc : 0.f;
        float w11 = (vy1 && vx1) ? wd : 0.f;
        const float2 v00 = *(const float2*)(fb + (size_t)(cy0*128 + cx0)*64 + 2*lane);
        const float2 v01 = *(const float2*)(fb + (size_t)(cy1*128 + cx0)*64 + 2*lane);
        const float2 v10 = *(const float2*)(fb + (size_t)(cy0*128 + cx1)*64 + 2*lane);
        const float2 v11 = *(const float2*)(fb + (size_t)(cy1*128 + cx1)*64 + 2*lane);
        float2 a;
        a.x = v00.x*w00 + v01.x*w01 + v10.x*w10 + v11.x*w11;
        a.y = v00.y*w00 + v01.y*w01 + v10.y*w10 + v11.y*w11;
        *(float2*)(ob + (size_t)x*64 + 2*lane) = a;
    }
}

// ---------------- K7: ROI align (grid (16,11); block 256) ----------------
__global__ __launch_bounds__(256) void k_roi(const float* __restrict__ box) {
    const int b = blockIdx.x, j = blockIdx.y;
    const float* feat; int r, cbase;
    if (j < 7)      { feat = g_fT;            r = j;          cbase = j*64; }
    else            { int t = j - 7;
                      feat = g_xtT[t >> 1];   r = t & 1;      cbase = 448 + t*64; }
    feat += (size_t)b*1048576;

    __shared__ float sly[46], shy[46], slx[46], shx[46];
    __shared__ int   sy0[46], sy1v[46], sx0[46], sx1v[46], syE[46], sxE[46];

    if (threadIdx.x < 46) {
        int s = threadIdx.x;
        float x1 = box[b*28 + r*4 + 0] * 0.25f;
        float y1 = box[b*28 + r*4 + 1] * 0.25f;
        float x2 = box[b*28 + r*4 + 2] * 0.25f;
        float y2 = box[b*28 + r*4 + 3] * 0.25f;
        float bw = fmaxf(x2 - x1, 1.0f) / 23.0f;
        float bh = fmaxf(y2 - y1, 1.0f) / 23.0f;
        float pos = (float)(s >> 1) + ((float)(s & 1) + 0.5f)*0.5f;
        float yv = y1 + pos*bh;
        float xv = x1 + pos*bw;
        syE[s] = (yv < -1.0f) || (yv > 128.0f);
        sxE[s] = (xv < -1.0f) || (xv > 128.0f);
        float yc = fminf(fmaxf(yv, 0.f), 127.f);
        float xc = fminf(fmaxf(xv, 0.f), 127.f);
        float y0f = floorf(yc), x0f = floorf(xc);
        sy0[s] = (int)y0f;  sx0[s] = (int)x0f;
        sy1v[s] = min((int)y0f + 1, 127);
        sx1v[s] = min((int)x0f + 1, 127);
        sly[s] = yc - y0f;  shy[s] = 1.f - sly[s];
        slx[s] = xc - x0f;  shx[s] = 1.f - slx[s];
    }
    __syncthreads();

    const int wid = threadIdx.x >> 5, lane = threadIdx.x & 31;
    float* outb = g_h + (size_t)b*529*704 + cbase + 2*lane;

    for (int cell = wid; cell < 529; cell += 8) {
        int ph = cell / 23, pw = cell - ph*23;
        float ax = 0.f, ay = 0.f;
        #pragma unroll
        for (int s = 0; s < 4; s++) {
            int sy = 2*ph + (s >> 1), sx = 2*pw + (s & 1);
            if (syE[sy] || sxE[sx]) continue;
            float hy = shy[sy], ly = sly[sy], hx = shx[sx], lx = slx[sx];
            int y0 = sy0[sy], y1i = sy1v[sy], x0 = sx0[sx], x1i = sx1v[sx];
            float w00 = hy*hx, w10 = hy*lx, w01 = ly*hx, w11 = ly*lx;
            const float2 v00 = *(const float2*)(feat + (size_t)(y0 *128 + x0 )*64 + 2*lane);
            const float2 v10 = *(const float2*)(feat + (size_t)(y0 *128 + x1i)*64 + 2*lane);
            const float2 v01 = *(const float2*)(feat + (size_t)(y1i*128 + x0 )*64 + 2*lane);
            const float2 v11 = *(const float2*)(feat + (size_t)(y1i*128 + x1i)*64 + 2*lane);
            ax += v00.x*w00 + v10.x*w10 + v01.x*w01 + v11.x*w11;
            ay += v00.y*w00 + v10.y*w10 + v01.y*w01 + v11.y*w11;
        }
        float2 o; o.x = ax*0.25f; o.y = ay*0.25f;
        *(float2*)(outb + (size_t)cell*704) = o;
    }
}

// ---------------- K8: transpose conv1_w -> [ic][k][oc] -------------------
__global__ void k_wt1(const float* __restrict__ w1) {
    int ic = blockIdx.x, t = threadIdx.x;
    if (t >= 576) return;
    int k = t >> 6, oc = t & 63;
    g_w1t[(ic*9 + k)*64 + oc] = w1[oc*6336 + ic*9 + k];
}

// ---------------- K9: conv1 3x3 704->64, implicit GEMM -------------------
// grid (21,16)=(oh,b); block 96: ocq=tid&15 (4 oc), owg=tid>>4 (4 ow)
__global__ __launch_bounds__(96) void k_conv1(const float* __restrict__ bias) {
    __shared__ float s_w[16*9*64];
    __shared__ float s_in[16*71 + 8];
    const int oh = blockIdx.x, b = blockIdx.y;
    const int tid = threadIdx.x;
    const int ocq = tid & 15;
    const int owg = tid >> 4;
    const int ow0 = 4*owg;

    float4 acc[4];
    #pragma unroll
    for (int p = 0; p < 4; p++) acc[p] = make_float4(0.f, 0.f, 0.f, 0.f);

    for (int ch = 0; ch < 44; ch++) {
        const int ic0 = ch * 16;
        __syncthreads();
        {
            const float4* src = (const float4*)(g_w1t + (size_t)ic0*576);
            float4* dst = (float4*)s_w;
            for (int i = tid; i < 2304; i += 96) dst[i] = src[i];
        }
        for (int i = tid; i < 16*69; i += 96) {
            int icl = i & 15, sp = i >> 4;
            int row = sp / 23, col = sp - row*23;
            s_in[icl*71 + sp] =
                g_h[((size_t)(b*529 + (oh + row)*23 + col))*704 + ic0 + icl];
        }
        __syncthreads();

        #pragma unroll 2
        for (int icl = 0; icl < 16; icl++) {
            const float* wp = s_w + icl*576 + ocq*4;
            const float* ip = s_in + icl*71 + ow0;
            #pragma unroll
            for (int kh = 0; kh < 3; kh++) {
                float in6[6];
                #pragma unroll
                for (int q = 0; q < 6; q++) in6[q] = ip[kh*23 + q];
                #pragma unroll
                for (int kw = 0; kw < 3; kw++) {
                    float4 w4 = *(const float4*)(wp + (kh*3 + kw)*64);
                    #pragma unroll
                    for (int p = 0; p < 4; p++) {
                        float iv = in6[kw + p];
                        acc[p].x = fmaf(w4.x, iv, acc[p].x);
                        acc[p].y = fmaf(w4.y, iv, acc[p].y);
                        acc[p].z = fmaf(w4.z, iv, acc[p].z);
                        acc[p].w = fmaf(w4.w, iv, acc[p].w);
                    }
                }
            }
        }
    }

    const int oc = 4*ocq;
    float b0 = bias[oc], b1 = bias[oc+1], b2 = bias[oc+2], b3 = bias[oc+3];
    #pragma unroll
    for (int p = 0; p < 4; p++) {
        int ow = ow0 + p;
        if (ow < 21) {
            size_t base = ((size_t)(b*64 + oc)*21 + oh)*21 + ow;
            g_c1[base        ] = acc[p].x + b0;
            g_c1[base + 441  ] = acc[p].y + b1;
            g_c1[base + 882  ] = acc[p].z + b2;
            g_c1[base + 1323 ] = acc[p].w + b3;
        }
    }
}

// ---------------- K10: conv1 BN stats + finalize (grid 64; block 256) ----
__global__ void k_stats1(const float* __restrict__ g, const float* __restrict__ bt) {
    const int c = blockIdx.x;
    float s = 0.f, q = 0.f;
    for (int i = threadIdx.x; i < 16*441; i += 256) {
        int b = i / 441, pix = i - b*441;
        float v = g_c1[(size_t)(b*64 + c)*441 + pix];
        s += v; q += v*v;
    }
    double ds = s, dq = q;
    for (int o = 16; o; o >>= 1) {
        ds += __shfl_down_sync(0xffffffffu, ds, o);
        dq += __shfl_down_sync(0xffffffffu, dq, o);
    }
    __shared__ double shs[8], shq[8];
    int lane = threadIdx.x & 31, wid = threadIdx.x >> 5;
    if (lane == 0) { shs[wid] = ds; shq[wid] = dq; }
    __syncthreads();
    if (threadIdx.x == 0) {
        double ts = 0, tq = 0;
        for (int i = 0; i < 8; i++) { ts += shs[i]; tq += shq[i]; }
        const double n = 7056.0;
        double m = ts / n, var = tq / n - m*m;
        double sc = (double)g[c] / sqrt(var + 1e-5);
        g_sc1[c] = (float)sc;
        g_sh1[c] = (float)((double)bt[c] - m*sc);
    }
}

// ---------------- K11: BN+ReLU+maxpool2/2 -> p1 --------------------------
__global__ void k_pool1() {
    int idx = blockIdx.x*256 + threadIdx.x;
    if (idx >= 16*64*100) return;
    int p = idx % 100; int bc = idx / 100;
    int c = bc & 63;
    int oh = p / 10, ow = p - oh*10;
    const float sc = g_sc1[c], sh = g_sh1[c];
    const float* src = g_c1 + (size_t)bc*441;
    float m = 0.f;
    #pragma unroll
    for (int kh = 0; kh < 2; kh++)
        #pragma unroll
        for (int kw = 0; kw < 2; kw++)
            m = fmaxf(m, fmaf(src[(2*oh+kh)*21 + 2*ow+kw], sc, sh));
    g_p1[idx] = m;
}

// ---------------- K12: conv2 3x3 64->32 + bias + relu (grid 16) ----------
__global__ void k_conv2(const float* __restrict__ w2, const float* __restrict__ b2) {
    __shared__ float s[6400];
    const int b = blockIdx.x;
    for (int i = threadIdx.x; i < 6400; i += 256)
        s[i] = g_p1[(size_t)b*6400 + i];
    __syncthreads();
    for (int o = threadIdx.x; o < 2048; o += 256) {
        int oc = o >> 6, pix = o & 63;
        int oh = pix >> 3, ow = pix & 7;
        float acc = b2[oc];
        for (int ic = 0; ic < 64; ic++) {
            const float* wp = w2 + (size_t)(oc*64 + ic)*9;
            const float* ip = s + ic*100 + oh*10 + ow;
            #pragma unroll
            for (int kh = 0; kh < 3; kh++)
                #pragma unroll
                for (int kw = 0; kw < 3; kw++)
                    acc = fmaf(ip[kh*10 + kw], wp[kh*3 + kw], acc);
        }
        g_c2[(size_t)b*2048 + o] = fmaxf(acc, 0.f);
    }
}

// ---------------- K13: fc1 2048->128 + relu (grid 16; block 256) ---------
__global__ void k_fc1(const float* __restrict__ w, const float* __restrict__ bs) {
    __shared__ float s[2048];
    const int b = blockIdx.x;
    for (int i = threadIdx.x; i < 2048; i += 256)
        s[i] = g_c2[(size_t)b*2048 + i];
    __syncthreads();
    int o = threadIdx.x;
    if (o < 128) {
        const float* wp = w + (size_t)o*2048;
        float acc = bs[o];
        #pragma unroll 4
        for (int i = 0; i < 2048; i++) acc = fmaf(s[i], wp[i], acc);
        g_fc[b*128 + o] = fmaxf(acc, 0.f);
    }
}

// ---------------- K14: head 128->12 + tanh (1 block 256) -----------------
__global__ void k_head(const float* __restrict__ w, const float* __restrict__ bs,
                       float* __restrict__ out) {
    __shared__ float s[2048];
    for (int i = threadIdx.x; i < 2048; i += 256) s[i] = g_fc[i];
    __syncthreads();
    int t = threadIdx.x;
    if (t < 192) {
        int b = t / 12, o = t - b*12;
        const float* wp = w + o*128;
        const float* xp = s + b*128;
        float acc = bs[o];
        #pragma unroll 4
        for (int i = 0; i < 128; i++) acc = fmaf(xp[i], wp[i], acc);
        out[t] = tanhf(acc);
    }
}

// ---------------- launch ---------------------------------------------------
extern "C" void kernel_launch(void* const* d_in, const int* in_sizes, int n_in,
                              void* d_out, int out_size) {
    const float* x       = (const float*)d_in[0];
    const float* box     = (const float*)d_in[1];
    const float* stem_w  = (const float*)d_in[2];
    const float* stem_g  = (const float*)d_in[3];
    const float* stem_b  = (const float*)d_in[4];
    const float* conv1_w = (const float*)d_in[5];
    const float* conv1_b = (const float*)d_in[6];
    const float* bn1_g   = (const float*)d_in[7];
    const float* bn1_b   = (const float*)d_in[8];
    const float* conv2_w = (const float*)d_in[9];
    const float* conv2_b = (const float*)d_in[10];
    const float* fc1_w   = (const float*)d_in[11];
    const float* fc1_b   = (const float*)d_in[12];
    const float* head_w  = (const float*)d_in[13];
    const float* head_b  = (const float*)d_in[14];
    float* out = (float*)d_out;

    cudaFuncSetAttribute(k_stemh, cudaFuncAttributeMaxDynamicSharedMemorySize,
                         STEM_SMEM);

    // slot order keeps k_stemh as the 4th launch so ncu (-s 5 -c 1) lands on it
    k_zero  <<<1, 64>>>();
    k_wt1   <<<704, 576>>>(conv1_w);
    k_zero  <<<1, 64>>>();
    k_stemh <<<dim3(2, 256, 16), 128, STEM_SMEM>>>(x, stem_w);
    k_fin0  <<<1, 64>>>(stem_g, stem_b);
    k_poolt <<<dim3(128, 16), 256>>>();
    k_gsample<<<dim3(16, 128, 2), 256>>>();
    k_roi   <<<dim3(16, 11), 256>>>(box);
    k_conv1 <<<dim3(21, 16), 96>>>(conv1_b);
    k_stats1<<<64, 256>>>(bn1_g, bn1_b);
    k_pool1 <<<(16*64*100 + 255)/256, 256>>>();
    k_conv2 <<<16, 256>>>(conv2_w, conv2_b);
    k_fc1   <<<16, 256>>>(fc1_w, fc1_b);
    k_head  <<<1, 256>>>(head_w, head_b, out);
}

// round 16
// speedup vs baseline: 1.1282x; 1.1282x over previous
#include <cuda_runtime.h>
#include <cuda_fp16.h>
#include <math.h>
#include <stdint.h>

// ---------------- workspace (device globals; allocations are forbidden) ----
__device__ __align__(16) __half g_stem_h[16*64*256*256]; // stem conv out, CHW fp16
__device__ __align__(16) float  g_fT  [16*128*128*64];   // f, HWC
__device__ __align__(16) float  g_xtT [2][16*128*128*64];// xt1/xt2, HWC
__device__ __align__(16) float  g_h   [16*529*704];      // roi concat, cell-major
__device__ __align__(16) float  g_c1  [16*64*441];       // conv1 out (b,oc,21,21)
__device__ __align__(16) float  g_p1  [16*64*100];       // pool1 out (b,oc,10,10)
__device__ __align__(16) float  g_c2  [16*2048];         // conv2 out flattened
__device__ __align__(16) float  g_fc  [16*128];
__device__ __align__(16) float  g_w1t [704*9*64];        // conv1_w transposed [ic][k][oc]
__device__ __align__(16) __half g_w0h [64*168];          // stem w, fp16 [oc][k(168)]
__device__ float g_ssum[64], g_ssq[64];
__device__ float g_sc0[64], g_sh0[64], g_sc1[64], g_sh1[64];

// ---------------- helpers -------------------------------------------------
__device__ __forceinline__ uint32_t smem_u32(const void* p) {
    uint32_t a;
    asm("{ .reg .u64 t; cvta.to.shared.u64 t, %1; cvt.u32.u64 %0, t; }"
        : "=r"(a) : "l"(p));
    return a;
}
__device__ __forceinline__ void ldsm4(uint32_t* r, uint32_t addr) {
    asm volatile("ldmatrix.sync.aligned.m8n8.x4.shared.b16 {%0,%1,%2,%3}, [%4];"
                 : "=r"(r[0]), "=r"(r[1]), "=r"(r[2]), "=r"(r[3]) : "r"(addr));
}
__device__ __forceinline__ void mma16816(float* d, const uint32_t* a,
                                         uint32_t b0, uint32_t b1) {
    asm volatile(
        "mma.sync.aligned.m16n8k16.row.col.f32.f16.f16.f32 "
        "{%0,%1,%2,%3}, {%4,%5,%6,%7}, {%8,%9}, {%0,%1,%2,%3};"
        : "+f"(d[0]), "+f"(d[1]), "+f"(d[2]), "+f"(d[3])
        : "r"(a[0]), "r"(a[1]), "r"(a[2]), "r"(a[3]), "r"(b0), "r"(b1));
}

// ---------------- K0: zero BN accumulators -------------------------------
__global__ void k_zero() {
    int t = threadIdx.x;
    if (t < 64) { g_ssum[t] = 0.f; g_ssq[t] = 0.f; }
}

// ---------------- K-1: stem weights -> fp16 [oc][168] (once) -------------
__global__ void k_wt0(const float* __restrict__ w) {
    int i = blockIdx.x * 256 + threadIdx.x;
    if (i >= 64 * 168) return;
    int oc = i / 168, k = i - oc * 168;
    float v = 0.f;
    if (k < 154) {
        int kh = k / 22, j = k - kh * 22;
        if (j < 21) {
            int kw = j / 3, c = j - kw * 3;
            v = w[oc * 147 + c * 49 + kh * 7 + kw];
        }
    }
    g_w0h[i] = __float2half_rn(v);
}

// ---------------- K1: stem conv 7x7 s2 p3 via HMMA (mma.sync f16) --------
// grid (2,256,16)=(ow half, oh, b); block 128 (4 warps); dyn smem 76032 B
#define SMO_A    512
#define SMO_B    43520
#define SMO_STG  65024
#define STEM_SMEM 76032
#define KLD 168            // padded K stride in halves (336 B)

__global__ __launch_bounds__(128) void k_stemh(const float* __restrict__ x) {
    extern __shared__ char smem[];
    const uint32_t sb = smem_u32(smem);
    float*  s_sum = (float*)(smem);
    float*  s_sq  = (float*)(smem + 256);
    __half* A     = (__half*)(smem + SMO_A);
    __half* stg   = (__half*)(smem + SMO_STG);

    const int half = blockIdx.x, oh = blockIdx.y, b = blockIdx.z;
    const int tid = threadIdx.x;
    const int wid = tid >> 5, lane = tid & 31;

    if (tid < 64) { s_sum[tid] = 0.f; s_sq[tid] = 0.f; }

    // B: straight fp16 copy from precomputed g_w0h (21504 B, no divisions)
    {
        const uint4* src = (const uint4*)g_w0h;
        uint4* dst = (uint4*)(smem + SMO_B);
        for (int i = tid; i < 1344; i += 128) dst[i] = src[i];
    }

    // stage input rows (fp16), division-free: validity of iw via c3 bounds
    {
        const int iw0 = 2 * (half * 128) - 3;
        const int lo = (iw0 < 0) ? (-iw0) * 3 : 0;             // c3 >= lo
        const int hi = ((512 - iw0) < 261 ? (512 - iw0) : 261) * 3; // c3 < hi
        #pragma unroll 1
        for (int kh = 0; kh < 7; kh++) {
            int ih = 2 * oh - 3 + kh;
            bool okh = (ih >= 0) && (ih < 512);
            const float* xr = x + (size_t)(b * 512 + ih) * 1536 + (size_t)iw0 * 3;
            __half* srow = stg + kh * 784;
            for (int c3 = tid; c3 < 784; c3 += 128) {
                float v = 0.f;
                if (okh && c3 >= lo && c3 < hi) v = xr[c3];
                srow[c3] = __float2half_rn(v);
            }
        }
    }
    __syncthreads();

    // im2col A[m][k], pure half2 copy: 21 contiguous stage halves @6m per kh
    {
        const int m = tid;
        #pragma unroll 1
        for (int kh = 0; kh < 7; kh++) {
            const __half* src = stg + kh * 784 + 6 * m;
            __half2 hv[10];
            #pragma unroll
            for (int j = 0; j < 10; j++) hv[j] = *(const __half2*)(src + 2 * j);
            __half v20 = src[20];
            __half2* dst = (__half2*)(A + m * KLD + kh * 22);
            #pragma unroll
            for (int j = 0; j < 10; j++) dst[j] = hv[j];
            dst[10] = __halves2half2(v20, __float2half_rn(0.f));
        }
        __half2* dt = (__half2*)(A + m * KLD + 154);
        #pragma unroll
        for (int t = 0; t < 3; t++) dt[t] = __float2half2_rn(0.f);
    }
    __syncthreads();

    // ---- HMMA mainloop: 10 k-steps of 16 ----
    float acc[2][8][4];
    #pragma unroll
    for (int mt = 0; mt < 2; mt++)
        #pragma unroll
        for (int nt = 0; nt < 8; nt++)
            #pragma unroll
            for (int q = 0; q < 4; q++) acc[mt][nt][q] = 0.f;

    uint32_t aAddr[2], bAddr[4];
    #pragma unroll
    for (int mt = 0; mt < 2; mt++) {
        int m0 = wid * 32 + mt * 16;
        aAddr[mt] = sb + SMO_A
                  + ((m0 + (lane & 15)) * KLD + (lane >> 4) * 8) * 2;
    }
    #pragma unroll
    for (int bt = 0; bt < 4; bt++) {
        int n0 = bt * 16;
        bAddr[bt] = sb + SMO_B
                  + ((n0 + ((lane >> 4) << 3) + (lane & 7)) * KLD
                     + ((lane >> 3) & 1) * 8) * 2;
    }

    #pragma unroll
    for (int ks = 0; ks < 10; ks++) {
        uint32_t ra[2][4], rb[4][4];
        ldsm4(ra[0], aAddr[0] + ks * 32);
        ldsm4(ra[1], aAddr[1] + ks * 32);
        #pragma unroll
        for (int bt = 0; bt < 4; bt++) ldsm4(rb[bt], bAddr[bt] + ks * 32);
        #pragma unroll
        for (int mt = 0; mt < 2; mt++)
            #pragma unroll
            for (int nt = 0; nt < 8; nt++)
                mma16816(acc[mt][nt], ra[mt],
                         rb[nt >> 1][(nt & 1) * 2], rb[nt >> 1][(nt & 1) * 2 + 1]);
    }

    // ---- epilogue: transpose through smem, coalesced fp16 STG + BN stats ----
    __syncthreads();
    float* s_out = (float*)(smem + SMO_A); // [64][132]
    {
        const int gr = lane >> 2;
        const int c2 = (lane & 3) * 2;
        #pragma unroll
        for (int mt = 0; mt < 2; mt++) {
            int m0 = wid * 32 + mt * 16 + gr;
            #pragma unroll
            for (int nt = 0; nt < 8; nt++) {
                int c = nt * 8 + c2;
                s_out[ c      * 132 + m0    ] = acc[mt][nt][0];
                s_out[(c + 1) * 132 + m0    ] = acc[mt][nt][1];
                s_out[ c      * 132 + m0 + 8] = acc[mt][nt][2];
                s_out[(c + 1) * 132 + m0 + 8] = acc[mt][nt][3];
            }
        }
    }
    __syncthreads();

    {
        const size_t rowbase = ((size_t)(b * 64) * 256 + oh) * 256
                             + half * 128 + 4 * lane;      // in halves
        #pragma unroll
        for (int ci = 0; ci < 16; ci++) {
            int c = wid * 16 + ci;
            float4 v = *(float4*)&s_out[c * 132 + 4 * lane];
            __half2 h01 = __floats2half2_rn(v.x, v.y);
            __half2 h23 = __floats2half2_rn(v.z, v.w);
            uint2 u = make_uint2(*(uint32_t*)&h01, *(uint32_t*)&h23);
            *(uint2*)(g_stem_h + rowbase + (size_t)c * 65536) = u;
        }
    }
    {
        int c = tid >> 1, part = tid & 1;
        const float* p = &s_out[c * 132 + part * 64];
        float s = 0.f, q = 0.f;
        #pragma unroll
        for (int i = 0; i < 16; i++) {
            float4 v = *(const float4*)(p + 4 * i);
            s += v.x + v.y + v.z + v.w;
            q += v.x*v.x + v.y*v.y + v.z*v.z + v.w*v.w;
        }
        s += __shfl_xor_sync(0xffffffffu, s, 1);
        q += __shfl_xor_sync(0xffffffffu, q, 1);
        if (part == 0) { atomicAdd(&s_sum[c], s); atomicAdd(&s_sq[c], q); }
    }
    __syncthreads();
    if (tid < 64) {
        atomicAdd(&g_ssum[tid], s_sum[tid]);
        atomicAdd(&g_ssq [tid], s_sq [tid]);
    }
}

// ---------------- K3: stem BN finalize -----------------------------------
__global__ void k_fin0(const float* __restrict__ g, const float* __restrict__ bt) {
    int c = threadIdx.x; if (c >= 64) return;
    const double n = 1048576.0;
    double m   = (double)g_ssum[c] / n;
    double var = (double)g_ssq[c] / n - m*m;
    double sc  = (double)g[c] / sqrt(var + 1e-5);
    g_sc0[c] = (float)sc;
    g_sh0[c] = (float)((double)bt[c] - m*sc);
}

// ---------------- K4: fused BN+ReLU+maxpool3/2/1 + CHW->HWC => g_fT ------
// grid (128,16)=(oh,b); block 256 (8 warps)
__global__ __launch_bounds__(256) void k_poolt() {
    __shared__ float s_t[128][65];
    const int oh = blockIdx.x, b = blockIdx.y;
    const int tid = threadIdx.x;
    const int wid = tid >> 5, lane = tid & 31;
    const __half* base = g_stem_h + (size_t)b * 64 * 65536;

    for (int c = wid; c < 64; c += 8) {
        const __half* pc = base + (size_t)c * 65536;
        const float sc = g_sc0[c], sh = g_sh0[c];
        #pragma unroll
        for (int k = 0; k < 4; k++) {
            int ow = lane + 32 * k;
            float m = 0.f;
            #pragma unroll
            for (int kh = 0; kh < 3; kh++) {
                int ih = 2*oh - 1 + kh; if (ih < 0 || ih > 255) continue;
                #pragma unroll
                for (int kw = 0; kw < 3; kw++) {
                    int iw = 2*ow - 1 + kw; if (iw < 0 || iw > 255) continue;
                    m = fmaxf(m, fmaf(__half2float(pc[ih*256 + iw]), sc, sh));
                }
            }
            s_t[ow][c] = m;
        }
    }
    __syncthreads();
    float* ob = g_fT + (size_t)b * 1048576 + (size_t)oh * 128 * 64;
    for (int i = tid; i < 8192; i += 256) {
        int ow = i >> 6, c = i & 63;
        ob[i] = s_t[ow][c];
    }
}

// ---------------- K6: grid_sample (grid (16,128,2); block 256) -----------
__global__ void k_gsample() {
    const int b = blockIdx.x, y = blockIdx.y, rot = blockIdx.z;
    const int wid = threadIdx.x >> 5, lane = threadIdx.x & 31;
    const float cosv = 0.99619469809174553f;
    const float sinv = 0.08715574274765817f;
    const float t01 = rot ? -sinv : sinv;
    const float gy  = (2*y + 1) / 128.0f - 1.0f;
    const float* fb = g_fT + (size_t)b*1048576;
    float* ob = g_xtT[rot] + (size_t)b*1048576 + (size_t)y*128*64;

    for (int x = wid; x < 128; x += 8) {
        float gx = (2*x + 1) / 128.0f - 1.0f;
        float u = gx*cosv + gy*t01;
        float v = -gx*t01 + gy*cosv;
        float ix = ((u + 1.f)*128.f - 1.f)*0.5f;
        float iy = ((v + 1.f)*128.f - 1.f)*0.5f;
        float x0f = floorf(ix), y0f = floorf(iy);
        int x0 = (int)x0f, y0 = (int)y0f;
        float wa = (x0f + 1 - ix)*(y0f + 1 - iy);
        float wb = (x0f + 1 - ix)*(iy - y0f);
        float wc = (ix - x0f)*(y0f + 1 - iy);
        float wd = (ix - x0f)*(iy - y0f);
        bool vx0 = (x0 >= 0) && (x0 < 128), vx1 = (x0+1 >= 0) && (x0+1 < 128);
        bool vy0 = (y0 >= 0) && (y0 < 128), vy1 = (y0+1 >= 0) && (y0+1 < 128);
        int cx0 = min(max(x0,0),127),   cx1 = min(max(x0+1,0),127);
        int cy0 = min(max(y0,0),127),   cy1 = min(max(y0+1,0),127);
        float w00 = (vy0 && vx0) ? wa : 0.f;
        float w01 = (vy1 && vx0) ? wb : 0.f;
        float w10 = (vy0 && vx1) ? wc : 0.f;
        float w11 = (vy1 && vx1) ? wd : 0.f;
        const float2 v00 = *(const float2*)(fb + (size_t)(cy0*128 + cx0)*64 + 2*lane);
        const float2 v01 = *(const float2*)(fb + (size_t)(cy1*128 + cx0)*64 + 2*lane);
        const float2 v10 = *(const float2*)(fb + (size_t)(cy0*128 + cx1)*64 + 2*lane);
        const float2 v11 = *(const float2*)(fb + (size_t)(cy1*128 + cx1)*64 + 2*lane);
        float2 a;
        a.x = v00.x*w00 + v01.x*w01 + v10.x*w10 + v11.x*w11;
        a.y = v00.y*w00 + v01.y*w01 + v10.y*w10 + v11.y*w11;
        *(float2*)(ob + (size_t)x*64 + 2*lane) = a;
    }
}

// ---------------- K7: ROI align (grid (16,11); block 256) ----------------
__global__ __launch_bounds__(256) void k_roi(const float* __restrict__ box) {
    const int b = blockIdx.x, j = blockIdx.y;
    const float* feat; int r, cbase;
    if (j < 7)      { feat = g_fT;            r = j;          cbase = j*64; }
    else            { int t = j - 7;
                      feat = g_xtT[t >> 1];   r = t & 1;      cbase = 448 + t*64; }
    feat += (size_t)b*1048576;

    __shared__ float sly[46], shy[46], slx[46], shx[46];
    __shared__ int   sy0[46], sy1v[46], sx0[46], sx1v[46], syE[46], sxE[46];

    if (threadIdx.x < 46) {
        int s = threadIdx.x;
        float x1 = box[b*28 + r*4 + 0] * 0.25f;
        float y1 = box[b*28 + r*4 + 1] * 0.25f;
        float x2 = box[b*28 + r*4 + 2] * 0.25f;
        float y2 = box[b*28 + r*4 + 3] * 0.25f;
        float bw = fmaxf(x2 - x1, 1.0f) / 23.0f;
        float bh = fmaxf(y2 - y1, 1.0f) / 23.0f;
        float pos = (float)(s >> 1) + ((float)(s & 1) + 0.5f)*0.5f;
        float yv = y1 + pos*bh;
        float xv = x1 + pos*bw;
        syE[s] = (yv < -1.0f) || (yv > 128.0f);
        sxE[s] = (xv < -1.0f) || (xv > 128.0f);
        float yc = fminf(fmaxf(yv, 0.f), 127.f);
        float xc = fminf(fmaxf(xv, 0.f), 127.f);
        float y0f = floorf(yc), x0f = floorf(xc);
        sy0[s] = (int)y0f;  sx0[s] = (int)x0f;
        sy1v[s] = min((int)y0f + 1, 127);
        sx1v[s] = min((int)x0f + 1, 127);
        sly[s] = yc - y0f;  shy[s] = 1.f - sly[s];
        slx[s] = xc - x0f;  shx[s] = 1.f - slx[s];
    }
    __syncthreads();

    const int wid = threadIdx.x >> 5, lane = threadIdx.x & 31;
    float* outb = g_h + (size_t)b*529*704 + cbase + 2*lane;

    for (int cell = wid; cell < 529; cell += 8) {
        int ph = cell / 23, pw = cell - ph*23;
        float ax = 0.f, ay = 0.f;
        #pragma unroll
        for (int s = 0; s < 4; s++) {
            int sy = 2*ph + (s >> 1), sx = 2*pw + (s & 1);
            if (syE[sy] || sxE[sx]) continue;
            float hy = shy[sy], ly = sly[sy], hx = shx[sx], lx = slx[sx];
            int y0 = sy0[sy], y1i = sy1v[sy], x0 = sx0[sx], x1i = sx1v[sx];
            float w00 = hy*hx, w10 = hy*lx, w01 = ly*hx, w11 = ly*lx;
            const float2 v00 = *(const float2*)(feat + (size_t)(y0 *128 + x0 )*64 + 2*lane);
            const float2 v10 = *(const float2*)(feat + (size_t)(y0 *128 + x1i)*64 + 2*lane);
            const float2 v01 = *(const float2*)(feat + (size_t)(y1i*128 + x0 )*64 + 2*lane);
            const float2 v11 = *(const float2*)(feat + (size_t)(y1i*128 + x1i)*64 + 2*lane);
            ax += v00.x*w00 + v10.x*w10 + v01.x*w01 + v11.x*w11;
            ay += v00.y*w00 + v10.y*w10 + v01.y*w01 + v11.y*w11;
        }
        float2 o; o.x = ax*0.25f; o.y = ay*0.25f;
        *(float2*)(outb + (size_t)cell*704) = o;
    }
}

// ---------------- K8: transpose conv1_w -> [ic][k][oc] -------------------
__global__ void k_wt1(const float* __restrict__ w1) {
    int ic = blockIdx.x, t = threadIdx.x;
    if (t >= 576) return;
    int k = t >> 6, oc = t & 63;
    g_w1t[(ic*9 + k)*64 + oc] = w1[oc*6336 + ic*9 + k];
}

// ---------------- K8b: init conv1 out with bias --------------------------
__global__ void k_c1init(const float* __restrict__ bias) {
    int idx = blockIdx.x * 256 + threadIdx.x;
    if (idx >= 16*64*441) return;
    int oc = (idx / 441) & 63;
    g_c1[idx] = bias[oc];
}

// ---------------- K9: conv1 3x3 704->64, implicit GEMM, split-K x4 -------
// grid (21,16,4)=(oh,b,kz); block 96: ocq=tid&15 (4 oc), owg=tid>>4 (4 ow)
__global__ __launch_bounds__(96) void k_conv1() {
    __shared__ float s_w[16*9*64];
    __shared__ float s_in[16*71 + 8];
    const int oh = blockIdx.x, b = blockIdx.y, kz = blockIdx.z;
    const int tid = threadIdx.x;
    const int ocq = tid & 15;
    const int owg = tid >> 4;
    const int ow0 = 4*owg;

    float4 acc[4];
    #pragma unroll
    for (int p = 0; p < 4; p++) acc[p] = make_float4(0.f, 0.f, 0.f, 0.f);

    for (int ch = kz*11; ch < kz*11 + 11; ch++) {
        const int ic0 = ch * 16;
        __syncthreads();
        {
            const float4* src = (const float4*)(g_w1t + (size_t)ic0*576);
            float4* dst = (float4*)s_w;
            for (int i = tid; i < 2304; i += 96) dst[i] = src[i];
        }
        for (int i = tid; i < 16*69; i += 96) {
            int icl = i & 15, sp = i >> 4;
            int row = sp / 23, col = sp - row*23;
            s_in[icl*71 + sp] =
                g_h[((size_t)(b*529 + (oh + row)*23 + col))*704 + ic0 + icl];
        }
        __syncthreads();

        #pragma unroll 2
        for (int icl = 0; icl < 16; icl++) {
            const float* wp = s_w + icl*576 + ocq*4;
            const float* ip = s_in + icl*71 + ow0;
            #pragma unroll
            for (int kh = 0; kh < 3; kh++) {
                float in6[6];
                #pragma unroll
                for (int q = 0; q < 6; q++) in6[q] = ip[kh*23 + q];
                #pragma unroll
                for (int kw = 0; kw < 3; kw++) {
                    float4 w4 = *(const float4*)(wp + (kh*3 + kw)*64);
                    #pragma unroll
                    for (int p = 0; p < 4; p++) {
                        float iv = in6[kw + p];
                        acc[p].x = fmaf(w4.x, iv, acc[p].x);
                        acc[p].y = fmaf(w4.y, iv, acc[p].y);
                        acc[p].z = fmaf(w4.z, iv, acc[p].z);
                        acc[p].w = fmaf(w4.w, iv, acc[p].w);
                    }
                }
            }
        }
    }

    const int oc = 4*ocq;
    #pragma unroll
    for (int p = 0; p < 4; p++) {
        int ow = ow0 + p;
        if (ow < 21) {
            size_t base = ((size_t)(b*64 + oc)*21 + oh)*21 + ow;
            atomicAdd(&g_c1[base        ], acc[p].x);
            atomicAdd(&g_c1[base + 441  ], acc[p].y);
            atomicAdd(&g_c1[base + 882  ], acc[p].z);
            atomicAdd(&g_c1[base + 1323 ], acc[p].w);
        }
    }
}

// ---------------- K10: conv1 BN stats + finalize (grid 64; block 256) ----
__global__ void k_stats1(const float* __restrict__ g, const float* __restrict__ bt) {
    const int c = blockIdx.x;
    float s = 0.f, q = 0.f;
    for (int i = threadIdx.x; i < 16*441; i += 256) {
        int b = i / 441, pix = i - b*441;
        float v = g_c1[(size_t)(b*64 + c)*441 + pix];
        s += v; q += v*v;
    }
    double ds = s, dq = q;
    for (int o = 16; o; o >>= 1) {
        ds += __shfl_down_sync(0xffffffffu, ds, o);
        dq += __shfl_down_sync(0xffffffffu, dq, o);
    }
    __shared__ double shs[8], shq[8];
    int lane = threadIdx.x & 31, wid = threadIdx.x >> 5;
    if (lane == 0) { shs[wid] = ds; shq[wid] = dq; }
    __syncthreads();
    if (threadIdx.x == 0) {
        double ts = 0, tq = 0;
        for (int i = 0; i < 8; i++) { ts += shs[i]; tq += shq[i]; }
        const double n = 7056.0;
        double m = ts / n, var = tq / n - m*m;
        double sc = (double)g[c] / sqrt(var + 1e-5);
        g_sc1[c] = (float)sc;
        g_sh1[c] = (float)((double)bt[c] - m*sc);
    }
}

// ---------------- K11: BN+ReLU+maxpool2/2 -> p1 --------------------------
__global__ void k_pool1() {
    int idx = blockIdx.x*256 + threadIdx.x;
    if (idx >= 16*64*100) return;
    int p = idx % 100; int bc = idx / 100;
    int c = bc & 63;
    int oh = p / 10, ow = p - oh*10;
    const float sc = g_sc1[c], sh = g_sh1[c];
    const float* src = g_c1 + (size_t)bc*441;
    float m = 0.f;
    #pragma unroll
    for (int kh = 0; kh < 2; kh++)
        #pragma unroll
        for (int kw = 0; kw < 2; kw++)
            m = fmaxf(m, fmaf(src[(2*oh+kh)*21 + 2*ow+kw], sc, sh));
    g_p1[idx] = m;
}

// ---------------- K12: conv2 3x3 64->32 + bias + relu (grid 16) ----------
__global__ void k_conv2(const float* __restrict__ w2, const float* __restrict__ b2) {
    __shared__ float s[6400];
    const int b = blockIdx.x;
    for (int i = threadIdx.x; i < 6400; i += 256)
        s[i] = g_p1[(size_t)b*6400 + i];
    __syncthreads();
    for (int o = threadIdx.x; o < 2048; o += 256) {
        int oc = o >> 6, pix = o & 63;
        int oh = pix >> 3, ow = pix & 7;
        float acc = b2[oc];
        for (int ic = 0; ic < 64; ic++) {
            const float* wp = w2 + (size_t)(oc*64 + ic)*9;
            const float* ip = s + ic*100 + oh*10 + ow;
            #pragma unroll
            for (int kh = 0; kh < 3; kh++)
                #pragma unroll
                for (int kw = 0; kw < 3; kw++)
                    acc = fmaf(ip[kh*10 + kw], wp[kh*3 + kw], acc);
        }
        g_c2[(size_t)b*2048 + o] = fmaxf(acc, 0.f);
    }
}

// ---------------- K13: fc1 2048->128 + relu (grid 16; block 256) ---------
__global__ void k_fc1(const float* __restrict__ w, const float* __restrict__ bs) {
    __shared__ float s[2048];
    const int b = blockIdx.x;
    for (int i = threadIdx.x; i < 2048; i += 256)
        s[i] = g_c2[(size_t)b*2048 + i];
    __syncthreads();
    int o = threadIdx.x;
    if (o < 128) {
        const float* wp = w + (size_t)o*2048;
        float acc = bs[o];
        #pragma unroll 4
        for (int i = 0; i < 2048; i++) acc = fmaf(s[i], wp[i], acc);
        g_fc[b*128 + o] = fmaxf(acc, 0.f);
    }
}

// ---------------- K14: head 128->12 + tanh (1 block 256) -----------------
__global__ void k_head(const float* __restrict__ w, const float* __restrict__ bs,
                       float* __restrict__ out) {
    __shared__ float s[2048];
    for (int i = threadIdx.x; i < 2048; i += 256) s[i] = g_fc[i];
    __syncthreads();
    int t = threadIdx.x;
    if (t < 192) {
        int b = t / 12, o = t - b*12;
        const float* wp = w + o*128;
        const float* xp = s + b*128;
        float acc = bs[o];
        #pragma unroll 4
        for (int i = 0; i < 128; i++) acc = fmaf(xp[i], wp[i], acc);
        out[t] = tanhf(acc);
    }
}

// ---------------- launch ---------------------------------------------------
extern "C" void kernel_launch(void* const* d_in, const int* in_sizes, int n_in,
                              void* d_out, int out_size) {
    const float* x       = (const float*)d_in[0];
    const float* box     = (const float*)d_in[1];
    const float* stem_w  = (const float*)d_in[2];
    const float* stem_g  = (const float*)d_in[3];
    const float* stem_b  = (const float*)d_in[4];
    const float* conv1_w = (const float*)d_in[5];
    const float* conv1_b = (const float*)d_in[6];
    const float* bn1_g   = (const float*)d_in[7];
    const float* bn1_b   = (const float*)d_in[8];
    const float* conv2_w = (const float*)d_in[9];
    const float* conv2_b = (const float*)d_in[10];
    const float* fc1_w   = (const float*)d_in[11];
    const float* fc1_b   = (const float*)d_in[12];
    const float* head_w  = (const float*)d_in[13];
    const float* head_b  = (const float*)d_in[14];
    float* out = (float*)d_out;

    cudaFuncSetAttribute(k_stemh, cudaFuncAttributeMaxDynamicSharedMemorySize,
                         STEM_SMEM);

    // slot order keeps k_stemh as the 4th launch so ncu (-s 5 -c 1) lands on it
    k_zero  <<<1, 64>>>();
    k_wt1   <<<704, 576>>>(conv1_w);
    k_wt0   <<<42, 256>>>(stem_w);
    k_stemh <<<dim3(2, 256, 16), 128, STEM_SMEM>>>(x);
    k_c1init<<<(16*64*441 + 255)/256, 256>>>(conv1_b);
    k_fin0  <<<1, 64>>>(stem_g, stem_b);
    k_poolt <<<dim3(128, 16), 256>>>();
    k_gsample<<<dim3(16, 128, 2), 256>>>();
    k_roi   <<<dim3(16, 11), 256>>>(box);
    k_conv1 <<<dim3(21, 16, 4), 96>>>();
    k_stats1<<<64, 256>>>(bn1_g, bn1_b);
    k_pool1 <<<(16*64*100 + 255)/256, 256>>>();
    k_conv2 <<<16, 256>>>(conv2_w, conv2_b);
    k_fc1   <<<16, 256>>>(fc1_w, fc1_b);
    k_head  <<<1, 256>>>(head_w, head_b, out);
}